// round 8
// baseline (speedup 1.0000x reference)
#include <cuda_runtime.h>
#include <cuda_bf16.h>
#include <cstdint>

// ---------------------------------------------------------------------------
// Problem constants
// ---------------------------------------------------------------------------
#define MTOK 65536          // tokens
#define CDIM 512
#define NHEADS 16
#define NWIN 1024
#define NW 64

// Scratch (device globals — no allocation allowed)
__device__ __nv_bfloat16 g_xnb [MTOK * CDIM];      // LN output (bf16 GEMM A)
__device__ float         g_qkv [MTOK * 3 * CDIM];  // qkv fp32
__device__ __nv_bfloat16 g_attb[MTOK * CDIM];      // attention out (bf16)
__device__ float         g_x2  [MTOK * CDIM];      // residual 1 (fp32)
__device__ __nv_bfloat16 g_hb  [MTOK * 4 * CDIM];  // fc1/gelu out (bf16)
__device__ __nv_bfloat16 g_wqkv [1536 * 512];
__device__ __nv_bfloat16 g_wproj[512 * 512];
__device__ __nv_bfloat16 g_wfc1 [2048 * 512];
__device__ __nv_bfloat16 g_wfc2 [512 * 2048];

// ---------------------------------------------------------------------------
// PTX helpers
// ---------------------------------------------------------------------------
__device__ __forceinline__ void cp_async16(uint32_t s, const void* g) {
    asm volatile("cp.async.cg.shared.global [%0], [%1], 16;\n" :: "r"(s), "l"(g));
}
__device__ __forceinline__ void cp_commit() {
    asm volatile("cp.async.commit_group;\n");
}
template<int N> __device__ __forceinline__ void cp_wait() {
    asm volatile("cp.async.wait_group %0;\n" :: "n"(N));
}
__device__ __forceinline__ uint32_t smem_u32(const void* p) {
    uint32_t a;
    asm("{ .reg .u64 t; cvta.to.shared.u64 t, %1; cvt.u32.u64 %0, t; }" : "=r"(a) : "l"(p));
    return a;
}
__device__ __forceinline__ void ldsm_x4(uint32_t& r0, uint32_t& r1, uint32_t& r2, uint32_t& r3,
                                        uint32_t addr) {
    asm volatile("ldmatrix.sync.aligned.m8n8.x4.shared.b16 {%0,%1,%2,%3}, [%4];"
                 : "=r"(r0), "=r"(r1), "=r"(r2), "=r"(r3) : "r"(addr));
}
__device__ __forceinline__ void mma_bf16(float c[4], const uint32_t a[4], const uint32_t b[2]) {
    asm volatile(
        "mma.sync.aligned.m16n8k16.row.col.f32.bf16.bf16.f32 "
        "{%0,%1,%2,%3},{%4,%5,%6,%7},{%8,%9},{%0,%1,%2,%3};\n"
        : "+f"(c[0]), "+f"(c[1]), "+f"(c[2]), "+f"(c[3])
        : "r"(a[0]), "r"(a[1]), "r"(a[2]), "r"(a[3]), "r"(b[0]), "r"(b[1]));
}
__device__ __forceinline__ float gelu_exact(float x) {
    return 0.5f * x * (1.0f + erff(x * 0.7071067811865475f));
}

// ---------------------------------------------------------------------------
// bf16 GEMM: Y[m][n] = sum_k A[m][k] * W[n][k] + bias[n] (+epi)
// OP: 0 = bias, 1 = bias + res(fp32), 2 = bias + exact GELU
// BM=BN=128, BK=32 halves (64B rows, XOR swizzle seg^=(row>>1)&3),
// 4-stage cp.async ring (64KB dynamic smem), one __syncthreads per K-slab.
// 4 warps (2x2), warp tile 64x64 via m16n8k16: per k16 slice 8 LDSM + 32 MMA.
// ---------------------------------------------------------------------------
template<int OP, typename OutT>
__global__ __launch_bounds__(128)
void gemm_bf16(const __nv_bfloat16* __restrict__ A, const __nv_bfloat16* __restrict__ W,
               const float* __restrict__ bias, const float* __restrict__ res,
               OutT* __restrict__ Y, int M, int N, int K) {
    constexpr int STAGE = 16384;              // A 8KB + B 8KB
    extern __shared__ __align__(1024) char tiles[];   // 4 * STAGE

    const int tid = threadIdx.x;
    const int bm = blockIdx.x * 128;
    const int bn = blockIdx.y * 128;
    const int warp = tid >> 5, lane = tid & 31;
    const int wm = (warp >> 1) * 64;
    const int wn = (warp & 1) * 64;
    const int fr = lane >> 2;
    const int fc2 = (lane & 3) * 2;

    float c[4][8][4];
#pragma unroll
    for (int mt = 0; mt < 4; mt++)
#pragma unroll
        for (int nt = 0; nt < 8; nt++)
#pragma unroll
            for (int r = 0; r < 4; r++) c[mt][nt][r] = 0.0f;

    const int nk = K >> 5;
    const uint32_t sbase = smem_u32(tiles);

    // loader: per stage A 128 rows + B 128 rows, 64B/row (4 x 16B segs).
    // 1024 chunks / 128 threads = 8 per thread. swizzle seg' = c ^ ((row>>1)&3)
    const int ldRow = tid >> 2;               // 0..31
    const int ldC   = tid & 3;
    auto load_tile = [&](int kt, int stage) {
        const int k0 = kt * 32;
        const uint32_t sb = sbase + stage * STAGE;
#pragma unroll
        for (int q = 0; q < 4; q++) {
            const int row = ldRow + q * 32;
            const int seg = ldC ^ ((row >> 1) & 3);
            cp_async16(sb + row * 64 + seg * 16,
                       A + (size_t)(bm + row) * K + k0 + ldC * 8);
            cp_async16(sb + 8192 + row * 64 + seg * 16,
                       W + (size_t)(bn + row) * K + k0 + ldC * 8);
        }
        cp_commit();
    };

    // per-thread ldmatrix offsets (byte, within stage)
    const int lRow = lane & 15;
    const int lSeg = lane >> 4;
    uint32_t offA[4][2], offB[4][2];
#pragma unroll
    for (int mt = 0; mt < 4; mt++) {
        const int row = wm + mt * 16 + lRow;
        const int sw = (row >> 1) & 3;
#pragma unroll
        for (int ks = 0; ks < 2; ks++)
            offA[mt][ks] = row * 64 + (((ks * 2 + lSeg) ^ sw) << 4);
    }
#pragma unroll
    for (int g = 0; g < 4; g++) {
        const int row = wn + g * 16 + lRow;
        const int sw = (row >> 1) & 3;
#pragma unroll
        for (int ks = 0; ks < 2; ks++)
            offB[g][ks] = 8192 + row * 64 + (((ks * 2 + lSeg) ^ sw) << 4);
    }

    load_tile(0, 0);
    load_tile(1, 1);
    load_tile(2, 2);

    for (int kt = 0; kt < nk; kt++) {
        const int rem = nk - kt - 1;          // groups committed after group kt
        if (rem >= 2)      cp_wait<2>();
        else if (rem == 1) cp_wait<1>();
        else               cp_wait<0>();
        __syncthreads();
        if (kt + 3 < nk) load_tile(kt + 3, (kt + 3) & 3);
        const uint32_t sb = sbase + (kt & 3) * STAGE;
#pragma unroll
        for (int ks = 0; ks < 2; ks++) {
            uint32_t af[4][4], bf[8][2];
#pragma unroll
            for (int mt = 0; mt < 4; mt++)
                ldsm_x4(af[mt][0], af[mt][1], af[mt][2], af[mt][3], sb + offA[mt][ks]);
#pragma unroll
            for (int g = 0; g < 4; g++)
                ldsm_x4(bf[2 * g][0], bf[2 * g + 1][0], bf[2 * g][1], bf[2 * g + 1][1],
                        sb + offB[g][ks]);
#pragma unroll
            for (int mt = 0; mt < 4; mt++)
#pragma unroll
                for (int nt = 0; nt < 8; nt++)
                    mma_bf16(c[mt][nt], af[mt], bf[nt]);
        }
    }

    // epilogue (m16n8 accum layout)
#pragma unroll
    for (int mt = 0; mt < 4; mt++) {
#pragma unroll
        for (int nt = 0; nt < 8; nt++) {
            const int n0 = bn + wn + nt * 8 + fc2;
            const float2 b2 = *(const float2*)&bias[n0];
#pragma unroll
            for (int half = 0; half < 2; half++) {
                const int m0 = bm + wm + mt * 16 + fr + half * 8;
                float v0 = c[mt][nt][half * 2 + 0] + b2.x;
                float v1 = c[mt][nt][half * 2 + 1] + b2.y;
                if constexpr (OP == 1) {
                    const float2 r2 = *(const float2*)&res[(size_t)m0 * N + n0];
                    v0 += r2.x; v1 += r2.y;
                }
                if constexpr (OP == 2) {
                    v0 = gelu_exact(v0); v1 = gelu_exact(v1);
                }
                if constexpr (sizeof(OutT) == 4) {
                    *(float2*)&Y[(size_t)m0 * N + n0] = make_float2(v0, v1);
                } else {
                    *(__nv_bfloat162*)&Y[(size_t)m0 * N + n0] = __floats2bfloat162_rn(v0, v1);
                }
            }
        }
    }
}

// ---------------------------------------------------------------------------
// fp32 -> bf16 weight conversion
// ---------------------------------------------------------------------------
__global__ __launch_bounds__(256)
void cvt_kernel(const float* __restrict__ in, __nv_bfloat16* __restrict__ out, int n4) {
    const int i = blockIdx.x * blockDim.x + threadIdx.x;
    if (i < n4) {
        const float4 v = ((const float4*)in)[i];
        ((__nv_bfloat162*)out)[i * 2]     = __floats2bfloat162_rn(v.x, v.y);
        ((__nv_bfloat162*)out)[i * 2 + 1] = __floats2bfloat162_rn(v.z, v.w);
    }
}

// ---------------------------------------------------------------------------
// LayerNorm -> bf16
// ---------------------------------------------------------------------------
__global__ __launch_bounds__(128)
void ln_kernel(const float* __restrict__ x, const float* __restrict__ g,
               const float* __restrict__ b, __nv_bfloat16* __restrict__ y) {
    const int row = blockIdx.x;
    const int t = threadIdx.x;
    const float4 v = ((const float4*)(x + (size_t)row * CDIM))[t];
    float s = v.x + v.y + v.z + v.w;
    float q = v.x * v.x + v.y * v.y + v.z * v.z + v.w * v.w;
#pragma unroll
    for (int o = 16; o; o >>= 1) {
        s += __shfl_xor_sync(0xffffffffu, s, o);
        q += __shfl_xor_sync(0xffffffffu, q, o);
    }
    __shared__ float ss[4], qq[4];
    if ((t & 31) == 0) { ss[t >> 5] = s; qq[t >> 5] = q; }
    __syncthreads();
    s = ss[0] + ss[1] + ss[2] + ss[3];
    q = qq[0] + qq[1] + qq[2] + qq[3];
    const float mean = s * (1.0f / CDIM);
    const float var = q * (1.0f / CDIM) - mean * mean;
    const float rstd = rsqrtf(var + 1e-5f);
    const float4 gg = ((const float4*)g)[t];
    const float4 bb = ((const float4*)b)[t];
    const float o0 = (v.x - mean) * rstd * gg.x + bb.x;
    const float o1 = (v.y - mean) * rstd * gg.y + bb.y;
    const float o2 = (v.z - mean) * rstd * gg.z + bb.z;
    const float o3 = (v.w - mean) * rstd * gg.w + bb.w;
    __nv_bfloat162* yp = (__nv_bfloat162*)(y + (size_t)row * CDIM);
    yp[t * 2]     = __floats2bfloat162_rn(o0, o1);
    yp[t * 2 + 1] = __floats2bfloat162_rn(o2, o3);
}

// ---------------------------------------------------------------------------
// Windowed attention (fp32 math, bf16 out)
// ---------------------------------------------------------------------------
__global__ __launch_bounds__(256)
void attn_kernel(const float* __restrict__ qkv, const float* __restrict__ D,
                 const float* __restrict__ a_p, const float* __restrict__ b_p,
                 const float* __restrict__ a_r, const float* __restrict__ b_r,
                 __nv_bfloat16* __restrict__ out) {
    __shared__ float  Dsh[64];
    __shared__ float2 csT[15][64];
    __shared__ float  ksh[64][36];
    __shared__ float  vsh[64][36];
    __shared__ float  psh[64][65];
    __shared__ float  phiT[15], arT[15], brT[15];

    const int t = threadIdx.x;
    const int w = blockIdx.x;
    const int bb = w >> 6;
    const int ww = w & 63;
    const int wy = ww >> 3, wx = ww & 7;

    if (t < 64) {
        const int y = wy * 8 + (t >> 3), xc = wx * 8 + (t & 7);
        Dsh[t] = D[bb * 4096 + y * 64 + xc];
    }
    __syncthreads();
    for (int e = t; e < 15 * 64; e += 256) {
        const int r7 = e >> 6, j = e & 63;
        const float ang = (float)(r7 - 7) * Dsh[j] * (6.283185307179586f / 256.0f);
        float sn, cs;
        sincosf(ang, &sn, &cs);
        csT[r7][j] = make_float2(cs, sn);
    }

    const int i  = t >> 2;
    const int lg = t & 3;
    const int y_i = wy * 8 + (i >> 3), x_i = wx * 8 + (i & 7);
    const long tok_i = (long)bb * 4096 + y_i * 64 + x_i;
    const int ri = i >> 3, ci = i & 7;

    for (int h = 0; h < NHEADS; h++) {
        __syncthreads();
        {
            const float* kg = qkv + tok_i * 1536 + 512 + h * 32 + lg * 8;
            const float* vg = kg + 512;
            const float4 k0 = ((const float4*)kg)[0], k1 = ((const float4*)kg)[1];
            const float4 v0 = ((const float4*)vg)[0], v1 = ((const float4*)vg)[1];
            *(float4*)&ksh[i][lg * 8]     = k0;
            *(float4*)&ksh[i][lg * 8 + 4] = k1;
            *(float4*)&vsh[i][lg * 8]     = v0;
            *(float4*)&vsh[i][lg * 8 + 4] = v1;
        }
        if (t < 15) {
            const int idx = (t + 8) % 15;
            const float azf = (float)(t - 7) * (6.283185307179586f / 64.0f);
            float sa, ca;
            sincosf(azf, &sa, &ca);
            phiT[t] = a_p[idx * NHEADS + h] * ca + b_p[idx * NHEADS + h] * sa;
            arT[t]  = a_r[idx * NHEADS + h];
            brT[t]  = b_r[idx * NHEADS + h];
        }
        float qv[32];
        {
            const float* qg = qkv + tok_i * 1536 + h * 32;
#pragma unroll
            for (int d4 = 0; d4 < 8; d4++) {
                const float4 qq = ((const float4*)qg)[d4];
                qv[d4 * 4 + 0] = qq.x * 0.17677669529663687f;
                qv[d4 * 4 + 1] = qq.y * 0.17677669529663687f;
                qv[d4 * 4 + 2] = qq.z * 0.17677669529663687f;
                qv[d4 * 4 + 3] = qq.w * 0.17677669529663687f;
            }
        }
        __syncthreads();

        float s[16];
#pragma unroll
        for (int jj = 0; jj < 16; jj++) {
            const int j = lg + 4 * jj;
            float acc = 0.0f;
#pragma unroll
            for (int d4 = 0; d4 < 8; d4++) {
                const float4 kk = *(const float4*)&ksh[j][d4 * 4];
                acc += qv[d4 * 4 + 0] * kk.x + qv[d4 * 4 + 1] * kk.y
                     + qv[d4 * 4 + 2] * kk.z + qv[d4 * 4 + 3] * kk.w;
            }
            const int r7 = ri - (j >> 3) + 7;
            const int a7 = ci - (j & 7) + 7;
            const float2 cp = csT[r7][j];
            acc += phiT[a7] + arT[r7] * cp.x + brT[r7] * cp.y;
            s[jj] = acc;
        }
        float mx = s[0];
#pragma unroll
        for (int jj = 1; jj < 16; jj++) mx = fmaxf(mx, s[jj]);
        mx = fmaxf(mx, __shfl_xor_sync(0xffffffffu, mx, 1));
        mx = fmaxf(mx, __shfl_xor_sync(0xffffffffu, mx, 2));
        float sum = 0.0f;
#pragma unroll
        for (int jj = 0; jj < 16; jj++) { s[jj] = __expf(s[jj] - mx); sum += s[jj]; }
        sum += __shfl_xor_sync(0xffffffffu, sum, 1);
        sum += __shfl_xor_sync(0xffffffffu, sum, 2);
        const float inv = 1.0f / sum;
#pragma unroll
        for (int jj = 0; jj < 16; jj++) psh[i][lg + 4 * jj] = s[jj] * inv;
        __syncwarp();

        float o[8];
#pragma unroll
        for (int r = 0; r < 8; r++) o[r] = 0.0f;
#pragma unroll
        for (int j = 0; j < 64; j++) {
            const float p = psh[i][j];
            const float4 v0 = *(const float4*)&vsh[j][lg * 8];
            const float4 v1 = *(const float4*)&vsh[j][lg * 8 + 4];
            o[0] += p * v0.x; o[1] += p * v0.y; o[2] += p * v0.z; o[3] += p * v0.w;
            o[4] += p * v1.x; o[5] += p * v1.y; o[6] += p * v1.z; o[7] += p * v1.w;
        }
        __nv_bfloat162* og = (__nv_bfloat162*)(out + tok_i * 512 + h * 32 + lg * 8);
        og[0] = __floats2bfloat162_rn(o[0], o[1]);
        og[1] = __floats2bfloat162_rn(o[2], o[3]);
        og[2] = __floats2bfloat162_rn(o[4], o[5]);
        og[3] = __floats2bfloat162_rn(o[6], o[7]);
    }
}

// ---------------------------------------------------------------------------
// Launch
// ---------------------------------------------------------------------------
#define GEMM_SMEM (4 * 16384)

extern "C" void kernel_launch(void* const* d_in, const int* in_sizes, int n_in,
                              void* d_out, int out_size) {
    const float* x      = (const float*)d_in[0];
    const float* D      = (const float*)d_in[1];
    const float* n1g    = (const float*)d_in[2];
    const float* n1b    = (const float*)d_in[3];
    const float* qkv_w  = (const float*)d_in[4];
    const float* qkv_b  = (const float*)d_in[5];
    const float* proj_w = (const float*)d_in[6];
    const float* proj_b = (const float*)d_in[7];
    const float* a_p    = (const float*)d_in[8];
    const float* b_p    = (const float*)d_in[9];
    const float* a_r    = (const float*)d_in[10];
    const float* b_r    = (const float*)d_in[11];
    const float* n2g    = (const float*)d_in[12];
    const float* n2b    = (const float*)d_in[13];
    const float* fc1_w  = (const float*)d_in[14];
    const float* fc1_b  = (const float*)d_in[15];
    const float* fc2_w  = (const float*)d_in[16];
    const float* fc2_b  = (const float*)d_in[17];
    float* out = (float*)d_out;

    __nv_bfloat16 *p_xnb, *p_attb, *p_hb, *p_wqkv, *p_wproj, *p_wfc1, *p_wfc2;
    float *p_qkv, *p_x2;
    cudaGetSymbolAddress((void**)&p_xnb,   g_xnb);
    cudaGetSymbolAddress((void**)&p_qkv,   g_qkv);
    cudaGetSymbolAddress((void**)&p_attb,  g_attb);
    cudaGetSymbolAddress((void**)&p_x2,    g_x2);
    cudaGetSymbolAddress((void**)&p_hb,    g_hb);
    cudaGetSymbolAddress((void**)&p_wqkv,  g_wqkv);
    cudaGetSymbolAddress((void**)&p_wproj, g_wproj);
    cudaGetSymbolAddress((void**)&p_wfc1,  g_wfc1);
    cudaGetSymbolAddress((void**)&p_wfc2,  g_wfc2);

    cudaFuncSetAttribute(gemm_bf16<0, float>,         cudaFuncAttributeMaxDynamicSharedMemorySize, GEMM_SMEM);
    cudaFuncSetAttribute(gemm_bf16<1, float>,         cudaFuncAttributeMaxDynamicSharedMemorySize, GEMM_SMEM);
    cudaFuncSetAttribute(gemm_bf16<2, __nv_bfloat16>, cudaFuncAttributeMaxDynamicSharedMemorySize, GEMM_SMEM);

    const int M = MTOK;

    // 0. weights -> bf16
    cvt_kernel<<<(1536 * 512 / 4 + 255) / 256, 256>>>(qkv_w,  p_wqkv,  1536 * 512 / 4);
    cvt_kernel<<<(512  * 512 / 4 + 255) / 256, 256>>>(proj_w, p_wproj, 512  * 512 / 4);
    cvt_kernel<<<(2048 * 512 / 4 + 255) / 256, 256>>>(fc1_w,  p_wfc1,  2048 * 512 / 4);
    cvt_kernel<<<(512 * 2048 / 4 + 255) / 256, 256>>>(fc2_w,  p_wfc2,  512 * 2048 / 4);

    // 1. LN1 -> bf16
    ln_kernel<<<M, 128>>>(x, n1g, n1b, p_xnb);
    // 2. QKV
    gemm_bf16<0, float><<<dim3(M / 128, 12), 128, GEMM_SMEM>>>(p_xnb, p_wqkv, qkv_b, nullptr, p_qkv, M, 1536, 512);
    // 3. attention
    attn_kernel<<<NWIN, 256>>>(p_qkv, D, a_p, b_p, a_r, b_r, p_attb);
    // 4. proj + residual(x)
    gemm_bf16<1, float><<<dim3(M / 128, 4), 128, GEMM_SMEM>>>(p_attb, p_wproj, proj_b, x, p_x2, M, 512, 512);
    // 5. LN2 -> bf16
    ln_kernel<<<M, 128>>>(p_x2, n2g, n2b, p_xnb);
    // 6. fc1 + GELU -> bf16
    gemm_bf16<2, __nv_bfloat16><<<dim3(M / 128, 16), 128, GEMM_SMEM>>>(p_xnb, p_wfc1, fc1_b, nullptr, p_hb, M, 2048, 512);
    // 7. fc2 + residual(x2) -> out
    gemm_bf16<1, float><<<dim3(M / 128, 4), 128, GEMM_SMEM>>>(p_hb, p_wfc2, fc2_b, p_x2, out, M, 512, 2048);
}

// round 10
// speedup vs baseline: 1.0991x; 1.0991x over previous
#include <cuda_runtime.h>
#include <cuda_bf16.h>
#include <cstdint>

// ---------------------------------------------------------------------------
// Problem constants
// ---------------------------------------------------------------------------
#define MTOK 65536          // tokens
#define CDIM 512
#define NHEADS 16
#define NWIN 1024
#define NW 64

// Scratch (device globals — no allocation allowed)
__device__ __nv_bfloat16 g_xnb [MTOK * CDIM];      // LN output (bf16 GEMM A)
__device__ float         g_qkv [MTOK * 3 * CDIM];  // qkv fp32
__device__ __nv_bfloat16 g_attb[MTOK * CDIM];      // attention out (bf16)
__device__ float         g_x2  [MTOK * CDIM];      // residual 1 (fp32)
__device__ __nv_bfloat16 g_hb  [MTOK * 4 * CDIM];  // fc1/gelu out (bf16)
__device__ __nv_bfloat16 g_wqkv [1536 * 512];
__device__ __nv_bfloat16 g_wproj[512 * 512];
__device__ __nv_bfloat16 g_wfc1 [2048 * 512];
__device__ __nv_bfloat16 g_wfc2 [512 * 2048];

// ---------------------------------------------------------------------------
// PTX helpers
// ---------------------------------------------------------------------------
__device__ __forceinline__ void cp_async16(uint32_t s, const void* g) {
    asm volatile("cp.async.cg.shared.global [%0], [%1], 16;\n" :: "r"(s), "l"(g));
}
__device__ __forceinline__ void cp_commit() {
    asm volatile("cp.async.commit_group;\n");
}
template<int N> __device__ __forceinline__ void cp_wait() {
    asm volatile("cp.async.wait_group %0;\n" :: "n"(N));
}
__device__ __forceinline__ uint32_t smem_u32(const void* p) {
    uint32_t a;
    asm("{ .reg .u64 t; cvta.to.shared.u64 t, %1; cvt.u32.u64 %0, t; }" : "=r"(a) : "l"(p));
    return a;
}
__device__ __forceinline__ void ldsm_x4(uint32_t& r0, uint32_t& r1, uint32_t& r2, uint32_t& r3,
                                        uint32_t addr) {
    asm volatile("ldmatrix.sync.aligned.m8n8.x4.shared.b16 {%0,%1,%2,%3}, [%4];"
                 : "=r"(r0), "=r"(r1), "=r"(r2), "=r"(r3) : "r"(addr));
}
__device__ __forceinline__ void mma_bf16(float c[4], const uint32_t a[4], const uint32_t b[2]) {
    asm volatile(
        "mma.sync.aligned.m16n8k16.row.col.f32.bf16.bf16.f32 "
        "{%0,%1,%2,%3},{%4,%5,%6,%7},{%8,%9},{%0,%1,%2,%3};\n"
        : "+f"(c[0]), "+f"(c[1]), "+f"(c[2]), "+f"(c[3])
        : "r"(a[0]), "r"(a[1]), "r"(a[2]), "r"(a[3]), "r"(b[0]), "r"(b[1]));
}
__device__ __forceinline__ float gelu_exact(float x) {
    return 0.5f * x * (1.0f + erff(x * 0.7071067811865475f));
}

// ---------------------------------------------------------------------------
// bf16 GEMM: Y[m][n] = sum_k A[m][k] * W[n][k] + bias[n] (+epi)
// OP: 0 = bias, 1 = bias + res(fp32), 2 = bias + exact GELU
// BM=BN=128, BK=64 halves (128B rows, 8x16B segs, XOR swizzle seg^=(row&7)),
// 3-stage cp.async ring in 96KB dynamic smem, one __syncthreads per 64-K slab.
// 8 warps (4 M x 2 N), warp tile 32x64 via m16n8k16 (R6-proven shape).
// ---------------------------------------------------------------------------
template<int OP, typename OutT>
__global__ __launch_bounds__(256, 2)
void gemm_bf16(const __nv_bfloat16* __restrict__ A, const __nv_bfloat16* __restrict__ W,
               const float* __restrict__ bias, const float* __restrict__ res,
               OutT* __restrict__ Y, int M, int N, int K) {
    constexpr int STAGE = 32768;              // A 16KB + B 16KB
    extern __shared__ __align__(1024) char tiles[];   // 3 * STAGE = 96KB

    const int tid = threadIdx.x;
    const int bm = blockIdx.x * 128;
    const int bn = blockIdx.y * 128;
    const int warp = tid >> 5, lane = tid & 31;
    const int wm = (warp >> 1) * 32;
    const int wn = (warp & 1) * 64;
    const int fr = lane >> 2;
    const int fc2 = (lane & 3) * 2;

    float c[2][8][4];
#pragma unroll
    for (int mt = 0; mt < 2; mt++)
#pragma unroll
        for (int nt = 0; nt < 8; nt++)
#pragma unroll
            for (int r = 0; r < 4; r++) c[mt][nt][r] = 0.0f;

    const int nk = K >> 6;                    // 64-wide K slabs
    const uint32_t sbase = smem_u32(tiles);

    // loader: per stage, A = 128 rows x 8 segs (16B), B same: 2048 chunks,
    // 8 per thread. store swizzle: seg' = c ^ (row & 7)
    const int ldRow = tid >> 3;               // 0..31
    const int ldC   = tid & 7;                // 16B seg within 128B row
    auto load_tile = [&](int kt, int stage) {
        const int k0 = kt * 64;
        const uint32_t sb = sbase + stage * STAGE;
#pragma unroll
        for (int q = 0; q < 4; q++) {
            const int row = ldRow + q * 32;
            const int seg = ldC ^ (row & 7);
            cp_async16(sb + row * 128 + seg * 16,
                       A + (size_t)(bm + row) * K + k0 + ldC * 8);
            cp_async16(sb + 16384 + row * 128 + seg * 16,
                       W + (size_t)(bn + row) * K + k0 + ldC * 8);
        }
        cp_commit();
    };

    // per-thread ldmatrix offsets (byte, within stage); ks = 16-col slice 0..3
    const int lRow = lane & 15;
    const int lSeg = lane >> 4;
    uint32_t offA[2][4], offB[4][4];
#pragma unroll
    for (int mt = 0; mt < 2; mt++) {
        const int row = wm + mt * 16 + lRow;
        const int sw = row & 7;
#pragma unroll
        for (int ks = 0; ks < 4; ks++)
            offA[mt][ks] = row * 128 + (((ks * 2 + lSeg) ^ sw) << 4);
    }
#pragma unroll
    for (int g = 0; g < 4; g++) {
        const int row = wn + g * 16 + lRow;
        const int sw = row & 7;
#pragma unroll
        for (int ks = 0; ks < 4; ks++)
            offB[g][ks] = 16384 + row * 128 + (((ks * 2 + lSeg) ^ sw) << 4);
    }

    load_tile(0, 0);
    if (nk > 1) load_tile(1, 1);

    for (int kt = 0; kt < nk; kt++) {
        if (kt < nk - 1) cp_wait<1>(); else cp_wait<0>();
        __syncthreads();
        if (kt + 2 < nk) load_tile(kt + 2, (kt + 2) % 3);
        const uint32_t sb = sbase + (kt % 3) * STAGE;
#pragma unroll
        for (int ks = 0; ks < 4; ks++) {
            uint32_t af[2][4], bf[8][2];
#pragma unroll
            for (int mt = 0; mt < 2; mt++)
                ldsm_x4(af[mt][0], af[mt][1], af[mt][2], af[mt][3], sb + offA[mt][ks]);
#pragma unroll
            for (int g = 0; g < 4; g++)
                ldsm_x4(bf[2 * g][0], bf[2 * g + 1][0], bf[2 * g][1], bf[2 * g + 1][1],
                        sb + offB[g][ks]);
#pragma unroll
            for (int mt = 0; mt < 2; mt++)
#pragma unroll
                for (int nt = 0; nt < 8; nt++)
                    mma_bf16(c[mt][nt], af[mt], bf[nt]);
        }
    }

    // epilogue (m16n8 accum layout)
#pragma unroll
    for (int mt = 0; mt < 2; mt++) {
#pragma unroll
        for (int nt = 0; nt < 8; nt++) {
            const int n0 = bn + wn + nt * 8 + fc2;
            const float2 b2 = *(const float2*)&bias[n0];
#pragma unroll
            for (int half = 0; half < 2; half++) {
                const int m0 = bm + wm + mt * 16 + fr + half * 8;
                float v0 = c[mt][nt][half * 2 + 0] + b2.x;
                float v1 = c[mt][nt][half * 2 + 1] + b2.y;
                if constexpr (OP == 1) {
                    const float2 r2 = *(const float2*)&res[(size_t)m0 * N + n0];
                    v0 += r2.x; v1 += r2.y;
                }
                if constexpr (OP == 2) {
                    v0 = gelu_exact(v0); v1 = gelu_exact(v1);
                }
                if constexpr (sizeof(OutT) == 4) {
                    *(float2*)&Y[(size_t)m0 * N + n0] = make_float2(v0, v1);
                } else {
                    *(__nv_bfloat162*)&Y[(size_t)m0 * N + n0] = __floats2bfloat162_rn(v0, v1);
                }
            }
        }
    }
}

// ---------------------------------------------------------------------------
// fp32 -> bf16 weight conversion
// ---------------------------------------------------------------------------
__global__ __launch_bounds__(256)
void cvt_kernel(const float* __restrict__ in, __nv_bfloat16* __restrict__ out, int n4) {
    const int i = blockIdx.x * blockDim.x + threadIdx.x;
    if (i < n4) {
        const float4 v = ((const float4*)in)[i];
        ((__nv_bfloat162*)out)[i * 2]     = __floats2bfloat162_rn(v.x, v.y);
        ((__nv_bfloat162*)out)[i * 2 + 1] = __floats2bfloat162_rn(v.z, v.w);
    }
}

// ---------------------------------------------------------------------------
// LayerNorm -> bf16
// ---------------------------------------------------------------------------
__global__ __launch_bounds__(128)
void ln_kernel(const float* __restrict__ x, const float* __restrict__ g,
               const float* __restrict__ b, __nv_bfloat16* __restrict__ y) {
    const int row = blockIdx.x;
    const int t = threadIdx.x;
    const float4 v = ((const float4*)(x + (size_t)row * CDIM))[t];
    float s = v.x + v.y + v.z + v.w;
    float q = v.x * v.x + v.y * v.y + v.z * v.z + v.w * v.w;
#pragma unroll
    for (int o = 16; o; o >>= 1) {
        s += __shfl_xor_sync(0xffffffffu, s, o);
        q += __shfl_xor_sync(0xffffffffu, q, o);
    }
    __shared__ float ss[4], qq[4];
    if ((t & 31) == 0) { ss[t >> 5] = s; qq[t >> 5] = q; }
    __syncthreads();
    s = ss[0] + ss[1] + ss[2] + ss[3];
    q = qq[0] + qq[1] + qq[2] + qq[3];
    const float mean = s * (1.0f / CDIM);
    const float var = q * (1.0f / CDIM) - mean * mean;
    const float rstd = rsqrtf(var + 1e-5f);
    const float4 gg = ((const float4*)g)[t];
    const float4 bb = ((const float4*)b)[t];
    const float o0 = (v.x - mean) * rstd * gg.x + bb.x;
    const float o1 = (v.y - mean) * rstd * gg.y + bb.y;
    const float o2 = (v.z - mean) * rstd * gg.z + bb.z;
    const float o3 = (v.w - mean) * rstd * gg.w + bb.w;
    __nv_bfloat162* yp = (__nv_bfloat162*)(y + (size_t)row * CDIM);
    yp[t * 2]     = __floats2bfloat162_rn(o0, o1);
    yp[t * 2 + 1] = __floats2bfloat162_rn(o2, o3);
}

// ---------------------------------------------------------------------------
// Windowed attention (fp32 math, bf16 out)
// ---------------------------------------------------------------------------
__global__ __launch_bounds__(256)
void attn_kernel(const float* __restrict__ qkv, const float* __restrict__ D,
                 const float* __restrict__ a_p, const float* __restrict__ b_p,
                 const float* __restrict__ a_r, const float* __restrict__ b_r,
                 __nv_bfloat16* __restrict__ out) {
    __shared__ float  Dsh[64];
    __shared__ float2 csT[15][64];
    __shared__ float  ksh[64][36];
    __shared__ float  vsh[64][36];
    __shared__ float  psh[64][65];
    __shared__ float  phiT[15], arT[15], brT[15];

    const int t = threadIdx.x;
    const int w = blockIdx.x;
    const int bb = w >> 6;
    const int ww = w & 63;
    const int wy = ww >> 3, wx = ww & 7;

    if (t < 64) {
        const int y = wy * 8 + (t >> 3), xc = wx * 8 + (t & 7);
        Dsh[t] = D[bb * 4096 + y * 64 + xc];
    }
    __syncthreads();
    for (int e = t; e < 15 * 64; e += 256) {
        const int r7 = e >> 6, j = e & 63;
        const float ang = (float)(r7 - 7) * Dsh[j] * (6.283185307179586f / 256.0f);
        float sn, cs;
        sincosf(ang, &sn, &cs);
        csT[r7][j] = make_float2(cs, sn);
    }

    const int i  = t >> 2;
    const int lg = t & 3;
    const int y_i = wy * 8 + (i >> 3), x_i = wx * 8 + (i & 7);
    const long tok_i = (long)bb * 4096 + y_i * 64 + x_i;
    const int ri = i >> 3, ci = i & 7;

    for (int h = 0; h < NHEADS; h++) {
        __syncthreads();
        {
            const float* kg = qkv + tok_i * 1536 + 512 + h * 32 + lg * 8;
            const float* vg = kg + 512;
            const float4 k0 = ((const float4*)kg)[0], k1 = ((const float4*)kg)[1];
            const float4 v0 = ((const float4*)vg)[0], v1 = ((const float4*)vg)[1];
            *(float4*)&ksh[i][lg * 8]     = k0;
            *(float4*)&ksh[i][lg * 8 + 4] = k1;
            *(float4*)&vsh[i][lg * 8]     = v0;
            *(float4*)&vsh[i][lg * 8 + 4] = v1;
        }
        if (t < 15) {
            const int idx = (t + 8) % 15;
            const float azf = (float)(t - 7) * (6.283185307179586f / 64.0f);
            float sa, ca;
            sincosf(azf, &sa, &ca);
            phiT[t] = a_p[idx * NHEADS + h] * ca + b_p[idx * NHEADS + h] * sa;
            arT[t]  = a_r[idx * NHEADS + h];
            brT[t]  = b_r[idx * NHEADS + h];
        }
        float qv[32];
        {
            const float* qg = qkv + tok_i * 1536 + h * 32;
#pragma unroll
            for (int d4 = 0; d4 < 8; d4++) {
                const float4 qq = ((const float4*)qg)[d4];
                qv[d4 * 4 + 0] = qq.x * 0.17677669529663687f;
                qv[d4 * 4 + 1] = qq.y * 0.17677669529663687f;
                qv[d4 * 4 + 2] = qq.z * 0.17677669529663687f;
                qv[d4 * 4 + 3] = qq.w * 0.17677669529663687f;
            }
        }
        __syncthreads();

        float s[16];
#pragma unroll
        for (int jj = 0; jj < 16; jj++) {
            const int j = lg + 4 * jj;
            float acc = 0.0f;
#pragma unroll
            for (int d4 = 0; d4 < 8; d4++) {
                const float4 kk = *(const float4*)&ksh[j][d4 * 4];
                acc += qv[d4 * 4 + 0] * kk.x + qv[d4 * 4 + 1] * kk.y
                     + qv[d4 * 4 + 2] * kk.z + qv[d4 * 4 + 3] * kk.w;
            }
            const int r7 = ri - (j >> 3) + 7;
            const int a7 = ci - (j & 7) + 7;
            const float2 cp = csT[r7][j];
            acc += phiT[a7] + arT[r7] * cp.x + brT[r7] * cp.y;
            s[jj] = acc;
        }
        float mx = s[0];
#pragma unroll
        for (int jj = 1; jj < 16; jj++) mx = fmaxf(mx, s[jj]);
        mx = fmaxf(mx, __shfl_xor_sync(0xffffffffu, mx, 1));
        mx = fmaxf(mx, __shfl_xor_sync(0xffffffffu, mx, 2));
        float sum = 0.0f;
#pragma unroll
        for (int jj = 0; jj < 16; jj++) { s[jj] = __expf(s[jj] - mx); sum += s[jj]; }
        sum += __shfl_xor_sync(0xffffffffu, sum, 1);
        sum += __shfl_xor_sync(0xffffffffu, sum, 2);
        const float inv = 1.0f / sum;
#pragma unroll
        for (int jj = 0; jj < 16; jj++) psh[i][lg + 4 * jj] = s[jj] * inv;
        __syncwarp();

        float o[8];
#pragma unroll
        for (int r = 0; r < 8; r++) o[r] = 0.0f;
#pragma unroll
        for (int j = 0; j < 64; j++) {
            const float p = psh[i][j];
            const float4 v0 = *(const float4*)&vsh[j][lg * 8];
            const float4 v1 = *(const float4*)&vsh[j][lg * 8 + 4];
            o[0] += p * v0.x; o[1] += p * v0.y; o[2] += p * v0.z; o[3] += p * v0.w;
            o[4] += p * v1.x; o[5] += p * v1.y; o[6] += p * v1.z; o[7] += p * v1.w;
        }
        __nv_bfloat162* og = (__nv_bfloat162*)(out + tok_i * 512 + h * 32 + lg * 8);
        og[0] = __floats2bfloat162_rn(o[0], o[1]);
        og[1] = __floats2bfloat162_rn(o[2], o[3]);
        og[2] = __floats2bfloat162_rn(o[4], o[5]);
        og[3] = __floats2bfloat162_rn(o[6], o[7]);
    }
}

// ---------------------------------------------------------------------------
// Launch
// ---------------------------------------------------------------------------
#define GEMM_SMEM (3 * 32768)

extern "C" void kernel_launch(void* const* d_in, const int* in_sizes, int n_in,
                              void* d_out, int out_size) {
    const float* x      = (const float*)d_in[0];
    const float* D      = (const float*)d_in[1];
    const float* n1g    = (const float*)d_in[2];
    const float* n1b    = (const float*)d_in[3];
    const float* qkv_w  = (const float*)d_in[4];
    const float* qkv_b  = (const float*)d_in[5];
    const float* proj_w = (const float*)d_in[6];
    const float* proj_b = (const float*)d_in[7];
    const float* a_p    = (const float*)d_in[8];
    const float* b_p    = (const float*)d_in[9];
    const float* a_r    = (const float*)d_in[10];
    const float* b_r    = (const float*)d_in[11];
    const float* n2g    = (const float*)d_in[12];
    const float* n2b    = (const float*)d_in[13];
    const float* fc1_w  = (const float*)d_in[14];
    const float* fc1_b  = (const float*)d_in[15];
    const float* fc2_w  = (const float*)d_in[16];
    const float* fc2_b  = (const float*)d_in[17];
    float* out = (float*)d_out;

    __nv_bfloat16 *p_xnb, *p_attb, *p_hb, *p_wqkv, *p_wproj, *p_wfc1, *p_wfc2;
    float *p_qkv, *p_x2;
    cudaGetSymbolAddress((void**)&p_xnb,   g_xnb);
    cudaGetSymbolAddress((void**)&p_qkv,   g_qkv);
    cudaGetSymbolAddress((void**)&p_attb,  g_attb);
    cudaGetSymbolAddress((void**)&p_x2,    g_x2);
    cudaGetSymbolAddress((void**)&p_hb,    g_hb);
    cudaGetSymbolAddress((void**)&p_wqkv,  g_wqkv);
    cudaGetSymbolAddress((void**)&p_wproj, g_wproj);
    cudaGetSymbolAddress((void**)&p_wfc1,  g_wfc1);
    cudaGetSymbolAddress((void**)&p_wfc2,  g_wfc2);

    cudaFuncSetAttribute(gemm_bf16<0, float>,         cudaFuncAttributeMaxDynamicSharedMemorySize, GEMM_SMEM);
    cudaFuncSetAttribute(gemm_bf16<1, float>,         cudaFuncAttributeMaxDynamicSharedMemorySize, GEMM_SMEM);
    cudaFuncSetAttribute(gemm_bf16<2, __nv_bfloat16>, cudaFuncAttributeMaxDynamicSharedMemorySize, GEMM_SMEM);

    const int M = MTOK;

    // 0. weights -> bf16
    cvt_kernel<<<(1536 * 512 / 4 + 255) / 256, 256>>>(qkv_w,  p_wqkv,  1536 * 512 / 4);
    cvt_kernel<<<(512  * 512 / 4 + 255) / 256, 256>>>(proj_w, p_wproj, 512  * 512 / 4);
    cvt_kernel<<<(2048 * 512 / 4 + 255) / 256, 256>>>(fc1_w,  p_wfc1,  2048 * 512 / 4);
    cvt_kernel<<<(512 * 2048 / 4 + 255) / 256, 256>>>(fc2_w,  p_wfc2,  512 * 2048 / 4);

    // 1. LN1 -> bf16
    ln_kernel<<<M, 128>>>(x, n1g, n1b, p_xnb);
    // 2. QKV
    gemm_bf16<0, float><<<dim3(M / 128, 12), 256, GEMM_SMEM>>>(p_xnb, p_wqkv, qkv_b, nullptr, p_qkv, M, 1536, 512);
    // 3. attention
    attn_kernel<<<NWIN, 256>>>(p_qkv, D, a_p, b_p, a_r, b_r, p_attb);
    // 4. proj + residual(x)
    gemm_bf16<1, float><<<dim3(M / 128, 4), 256, GEMM_SMEM>>>(p_attb, p_wproj, proj_b, x, p_x2, M, 512, 512);
    // 5. LN2 -> bf16
    ln_kernel<<<M, 128>>>(p_x2, n2g, n2b, p_xnb);
    // 6. fc1 + GELU -> bf16
    gemm_bf16<2, __nv_bfloat16><<<dim3(M / 128, 16), 256, GEMM_SMEM>>>(p_xnb, p_wfc1, fc1_b, nullptr, p_hb, M, 2048, 512);
    // 7. fc2 + residual(x2) -> out
    gemm_bf16<1, float><<<dim3(M / 128, 4), 256, GEMM_SMEM>>>(p_hb, p_wfc2, fc2_b, p_x2, out, M, 512, 2048);
}

// round 12
// speedup vs baseline: 1.1002x; 1.0010x over previous
#include <cuda_runtime.h>
#include <cuda_bf16.h>
#include <cstdint>

// ---------------------------------------------------------------------------
// Problem constants
// ---------------------------------------------------------------------------
#define MTOK 65536          // tokens
#define CDIM 512
#define NHEADS 16
#define NWIN 1024
#define NW 64

// Scratch (device globals — no allocation allowed)
__device__ __nv_bfloat16 g_xnb [MTOK * CDIM];      // LN output (bf16 GEMM A)
__device__ float         g_qkv [MTOK * 3 * CDIM];  // qkv fp32
__device__ __nv_bfloat16 g_attb[MTOK * CDIM];      // attention out (bf16)
__device__ float         g_x2  [MTOK * CDIM];      // residual 1 (fp32)
__device__ __nv_bfloat16 g_hb  [MTOK * 4 * CDIM];  // fc1/gelu out (bf16)
__device__ __nv_bfloat16 g_wqkv [1536 * 512];
__device__ __nv_bfloat16 g_wproj[512 * 512];
__device__ __nv_bfloat16 g_wfc1 [2048 * 512];
__device__ __nv_bfloat16 g_wfc2 [512 * 2048];

// ---------------------------------------------------------------------------
// PTX helpers
// ---------------------------------------------------------------------------
__device__ __forceinline__ void cp_async16(uint32_t s, const void* g) {
    asm volatile("cp.async.cg.shared.global [%0], [%1], 16;\n" :: "r"(s), "l"(g));
}
__device__ __forceinline__ void cp_commit() {
    asm volatile("cp.async.commit_group;\n");
}
template<int N> __device__ __forceinline__ void cp_wait() {
    asm volatile("cp.async.wait_group %0;\n" :: "n"(N));
}
__device__ __forceinline__ uint32_t smem_u32(const void* p) {
    uint32_t a;
    asm("{ .reg .u64 t; cvta.to.shared.u64 t, %1; cvt.u32.u64 %0, t; }" : "=r"(a) : "l"(p));
    return a;
}
__device__ __forceinline__ void ldsm_x4(uint32_t& r0, uint32_t& r1, uint32_t& r2, uint32_t& r3,
                                        uint32_t addr) {
    asm volatile("ldmatrix.sync.aligned.m8n8.x4.shared.b16 {%0,%1,%2,%3}, [%4];"
                 : "=r"(r0), "=r"(r1), "=r"(r2), "=r"(r3) : "r"(addr));
}
__device__ __forceinline__ void mma_bf16(float c[4], const uint32_t a[4], const uint32_t b[2]) {
    asm volatile(
        "mma.sync.aligned.m16n8k16.row.col.f32.bf16.bf16.f32 "
        "{%0,%1,%2,%3},{%4,%5,%6,%7},{%8,%9},{%0,%1,%2,%3};\n"
        : "+f"(c[0]), "+f"(c[1]), "+f"(c[2]), "+f"(c[3])
        : "r"(a[0]), "r"(a[1]), "r"(a[2]), "r"(a[3]), "r"(b[0]), "r"(b[1]));
}
__device__ __forceinline__ float gelu_exact(float x) {
    return 0.5f * x * (1.0f + erff(x * 0.7071067811865475f));
}

// ---------------------------------------------------------------------------
// bf16 GEMM: Y[m][n] = sum_k A[m][k] * W[n][k] + bias[n] (+epi)
// OP: 0 = bias, 1 = bias + res(fp32), 2 = bias + exact GELU
// GRID IS (N/128, M/128): blockIdx.x = N-tile (fast-varying) so that all
// N-tiles of one M-band are co-resident and share the A tile via L2;
// weights are small enough to be L2-resident across M-bands.
// BM=BN=128, BK=64 halves (128B rows, 8x16B segs, XOR swizzle seg^=(row&7)),
// 3-stage cp.async ring in 96KB dynamic smem, one __syncthreads per 64-K slab.
// 8 warps (4 M x 2 N), warp tile 32x64 via m16n8k16.
// ---------------------------------------------------------------------------
template<int OP, typename OutT>
__global__ __launch_bounds__(256, 2)
void gemm_bf16(const __nv_bfloat16* __restrict__ A, const __nv_bfloat16* __restrict__ W,
               const float* __restrict__ bias, const float* __restrict__ res,
               OutT* __restrict__ Y, int M, int N, int K) {
    constexpr int STAGE = 32768;              // A 16KB + B 16KB
    extern __shared__ __align__(1024) char tiles[];   // 3 * STAGE = 96KB

    const int tid = threadIdx.x;
    const int bm = blockIdx.y * 128;          // M-band (slow-varying)
    const int bn = blockIdx.x * 128;          // N-tile (fast-varying)
    const int warp = tid >> 5, lane = tid & 31;
    const int wm = (warp >> 1) * 32;
    const int wn = (warp & 1) * 64;
    const int fr = lane >> 2;
    const int fc2 = (lane & 3) * 2;

    float c[2][8][4];
#pragma unroll
    for (int mt = 0; mt < 2; mt++)
#pragma unroll
        for (int nt = 0; nt < 8; nt++)
#pragma unroll
            for (int r = 0; r < 4; r++) c[mt][nt][r] = 0.0f;

    const int nk = K >> 6;                    // 64-wide K slabs
    const uint32_t sbase = smem_u32(tiles);

    // loader: per stage, A = 128 rows x 8 segs (16B), B same: 2048 chunks,
    // 8 per thread. store swizzle: seg' = c ^ (row & 7)
    const int ldRow = tid >> 3;               // 0..31
    const int ldC   = tid & 7;                // 16B seg within 128B row
    auto load_tile = [&](int kt, int stage) {
        const int k0 = kt * 64;
        const uint32_t sb = sbase + stage * STAGE;
#pragma unroll
        for (int q = 0; q < 4; q++) {
            const int row = ldRow + q * 32;
            const int seg = ldC ^ (row & 7);
            cp_async16(sb + row * 128 + seg * 16,
                       A + (size_t)(bm + row) * K + k0 + ldC * 8);
            cp_async16(sb + 16384 + row * 128 + seg * 16,
                       W + (size_t)(bn + row) * K + k0 + ldC * 8);
        }
        cp_commit();
    };

    // per-thread ldmatrix offsets (byte, within stage); ks = 16-col slice 0..3
    const int lRow = lane & 15;
    const int lSeg = lane >> 4;
    uint32_t offA[2][4], offB[4][4];
#pragma unroll
    for (int mt = 0; mt < 2; mt++) {
        const int row = wm + mt * 16 + lRow;
        const int sw = row & 7;
#pragma unroll
        for (int ks = 0; ks < 4; ks++)
            offA[mt][ks] = row * 128 + (((ks * 2 + lSeg) ^ sw) << 4);
    }
#pragma unroll
    for (int g = 0; g < 4; g++) {
        const int row = wn + g * 16 + lRow;
        const int sw = row & 7;
#pragma unroll
        for (int ks = 0; ks < 4; ks++)
            offB[g][ks] = 16384 + row * 128 + (((ks * 2 + lSeg) ^ sw) << 4);
    }

    load_tile(0, 0);
    if (nk > 1) load_tile(1, 1);

    for (int kt = 0; kt < nk; kt++) {
        if (kt < nk - 1) cp_wait<1>(); else cp_wait<0>();
        __syncthreads();
        if (kt + 2 < nk) load_tile(kt + 2, (kt + 2) % 3);
        const uint32_t sb = sbase + (kt % 3) * STAGE;
#pragma unroll
        for (int ks = 0; ks < 4; ks++) {
            uint32_t af[2][4], bf[8][2];
#pragma unroll
            for (int mt = 0; mt < 2; mt++)
                ldsm_x4(af[mt][0], af[mt][1], af[mt][2], af[mt][3], sb + offA[mt][ks]);
#pragma unroll
            for (int g = 0; g < 4; g++)
                ldsm_x4(bf[2 * g][0], bf[2 * g + 1][0], bf[2 * g][1], bf[2 * g + 1][1],
                        sb + offB[g][ks]);
#pragma unroll
            for (int mt = 0; mt < 2; mt++)
#pragma unroll
                for (int nt = 0; nt < 8; nt++)
                    mma_bf16(c[mt][nt], af[mt], bf[nt]);
        }
    }

    // epilogue (m16n8 accum layout)
#pragma unroll
    for (int mt = 0; mt < 2; mt++) {
#pragma unroll
        for (int nt = 0; nt < 8; nt++) {
            const int n0 = bn + wn + nt * 8 + fc2;
            const float2 b2 = *(const float2*)&bias[n0];
#pragma unroll
            for (int half = 0; half < 2; half++) {
                const int m0 = bm + wm + mt * 16 + fr + half * 8;
                float v0 = c[mt][nt][half * 2 + 0] + b2.x;
                float v1 = c[mt][nt][half * 2 + 1] + b2.y;
                if constexpr (OP == 1) {
                    const float2 r2 = *(const float2*)&res[(size_t)m0 * N + n0];
                    v0 += r2.x; v1 += r2.y;
                }
                if constexpr (OP == 2) {
                    v0 = gelu_exact(v0); v1 = gelu_exact(v1);
                }
                if constexpr (sizeof(OutT) == 4) {
                    *(float2*)&Y[(size_t)m0 * N + n0] = make_float2(v0, v1);
                } else {
                    *(__nv_bfloat162*)&Y[(size_t)m0 * N + n0] = __floats2bfloat162_rn(v0, v1);
                }
            }
        }
    }
}

// ---------------------------------------------------------------------------
// fp32 -> bf16 weight conversion
// ---------------------------------------------------------------------------
__global__ __launch_bounds__(256)
void cvt_kernel(const float* __restrict__ in, __nv_bfloat16* __restrict__ out, int n4) {
    const int i = blockIdx.x * blockDim.x + threadIdx.x;
    if (i < n4) {
        const float4 v = ((const float4*)in)[i];
        ((__nv_bfloat162*)out)[i * 2]     = __floats2bfloat162_rn(v.x, v.y);
        ((__nv_bfloat162*)out)[i * 2 + 1] = __floats2bfloat162_rn(v.z, v.w);
    }
}

// ---------------------------------------------------------------------------
// LayerNorm -> bf16
// ---------------------------------------------------------------------------
__global__ __launch_bounds__(128)
void ln_kernel(const float* __restrict__ x, const float* __restrict__ g,
               const float* __restrict__ b, __nv_bfloat16* __restrict__ y) {
    const int row = blockIdx.x;
    const int t = threadIdx.x;
    const float4 v = ((const float4*)(x + (size_t)row * CDIM))[t];
    float s = v.x + v.y + v.z + v.w;
    float q = v.x * v.x + v.y * v.y + v.z * v.z + v.w * v.w;
#pragma unroll
    for (int o = 16; o; o >>= 1) {
        s += __shfl_xor_sync(0xffffffffu, s, o);
        q += __shfl_xor_sync(0xffffffffu, q, o);
    }
    __shared__ float ss[4], qq[4];
    if ((t & 31) == 0) { ss[t >> 5] = s; qq[t >> 5] = q; }
    __syncthreads();
    s = ss[0] + ss[1] + ss[2] + ss[3];
    q = qq[0] + qq[1] + qq[2] + qq[3];
    const float mean = s * (1.0f / CDIM);
    const float var = q * (1.0f / CDIM) - mean * mean;
    const float rstd = rsqrtf(var + 1e-5f);
    const float4 gg = ((const float4*)g)[t];
    const float4 bb = ((const float4*)b)[t];
    const float o0 = (v.x - mean) * rstd * gg.x + bb.x;
    const float o1 = (v.y - mean) * rstd * gg.y + bb.y;
    const float o2 = (v.z - mean) * rstd * gg.z + bb.z;
    const float o3 = (v.w - mean) * rstd * gg.w + bb.w;
    __nv_bfloat162* yp = (__nv_bfloat162*)(y + (size_t)row * CDIM);
    yp[t * 2]     = __floats2bfloat162_rn(o0, o1);
    yp[t * 2 + 1] = __floats2bfloat162_rn(o2, o3);
}

// ---------------------------------------------------------------------------
// Windowed attention (fp32 math, bf16 out)
// ---------------------------------------------------------------------------
__global__ __launch_bounds__(256)
void attn_kernel(const float* __restrict__ qkv, const float* __restrict__ D,
                 const float* __restrict__ a_p, const float* __restrict__ b_p,
                 const float* __restrict__ a_r, const float* __restrict__ b_r,
                 __nv_bfloat16* __restrict__ out) {
    __shared__ float  Dsh[64];
    __shared__ float2 csT[15][64];
    __shared__ float  ksh[64][36];
    __shared__ float  vsh[64][36];
    __shared__ float  psh[64][65];
    __shared__ float  phiT[15], arT[15], brT[15];

    const int t = threadIdx.x;
    const int w = blockIdx.x;
    const int bb = w >> 6;
    const int ww = w & 63;
    const int wy = ww >> 3, wx = ww & 7;

    if (t < 64) {
        const int y = wy * 8 + (t >> 3), xc = wx * 8 + (t & 7);
        Dsh[t] = D[bb * 4096 + y * 64 + xc];
    }
    __syncthreads();
    for (int e = t; e < 15 * 64; e += 256) {
        const int r7 = e >> 6, j = e & 63;
        const float ang = (float)(r7 - 7) * Dsh[j] * (6.283185307179586f / 256.0f);
        float sn, cs;
        sincosf(ang, &sn, &cs);
        csT[r7][j] = make_float2(cs, sn);
    }

    const int i  = t >> 2;
    const int lg = t & 3;
    const int y_i = wy * 8 + (i >> 3), x_i = wx * 8 + (i & 7);
    const long tok_i = (long)bb * 4096 + y_i * 64 + x_i;
    const int ri = i >> 3, ci = i & 7;

    for (int h = 0; h < NHEADS; h++) {
        __syncthreads();
        {
            const float* kg = qkv + tok_i * 1536 + 512 + h * 32 + lg * 8;
            const float* vg = kg + 512;
            const float4 k0 = ((const float4*)kg)[0], k1 = ((const float4*)kg)[1];
            const float4 v0 = ((const float4*)vg)[0], v1 = ((const float4*)vg)[1];
            *(float4*)&ksh[i][lg * 8]     = k0;
            *(float4*)&ksh[i][lg * 8 + 4] = k1;
            *(float4*)&vsh[i][lg * 8]     = v0;
            *(float4*)&vsh[i][lg * 8 + 4] = v1;
        }
        if (t < 15) {
            const int idx = (t + 8) % 15;
            const float azf = (float)(t - 7) * (6.283185307179586f / 64.0f);
            float sa, ca;
            sincosf(azf, &sa, &ca);
            phiT[t] = a_p[idx * NHEADS + h] * ca + b_p[idx * NHEADS + h] * sa;
            arT[t]  = a_r[idx * NHEADS + h];
            brT[t]  = b_r[idx * NHEADS + h];
        }
        float qv[32];
        {
            const float* qg = qkv + tok_i * 1536 + h * 32;
#pragma unroll
            for (int d4 = 0; d4 < 8; d4++) {
                const float4 qq = ((const float4*)qg)[d4];
                qv[d4 * 4 + 0] = qq.x * 0.17677669529663687f;
                qv[d4 * 4 + 1] = qq.y * 0.17677669529663687f;
                qv[d4 * 4 + 2] = qq.z * 0.17677669529663687f;
                qv[d4 * 4 + 3] = qq.w * 0.17677669529663687f;
            }
        }
        __syncthreads();

        float s[16];
#pragma unroll
        for (int jj = 0; jj < 16; jj++) {
            const int j = lg + 4 * jj;
            float acc = 0.0f;
#pragma unroll
            for (int d4 = 0; d4 < 8; d4++) {
                const float4 kk = *(const float4*)&ksh[j][d4 * 4];
                acc += qv[d4 * 4 + 0] * kk.x + qv[d4 * 4 + 1] * kk.y
                     + qv[d4 * 4 + 2] * kk.z + qv[d4 * 4 + 3] * kk.w;
            }
            const int r7 = ri - (j >> 3) + 7;
            const int a7 = ci - (j & 7) + 7;
            const float2 cp = csT[r7][j];
            acc += phiT[a7] + arT[r7] * cp.x + brT[r7] * cp.y;
            s[jj] = acc;
        }
        float mx = s[0];
#pragma unroll
        for (int jj = 1; jj < 16; jj++) mx = fmaxf(mx, s[jj]);
        mx = fmaxf(mx, __shfl_xor_sync(0xffffffffu, mx, 1));
        mx = fmaxf(mx, __shfl_xor_sync(0xffffffffu, mx, 2));
        float sum = 0.0f;
#pragma unroll
        for (int jj = 0; jj < 16; jj++) { s[jj] = __expf(s[jj] - mx); sum += s[jj]; }
        sum += __shfl_xor_sync(0xffffffffu, sum, 1);
        sum += __shfl_xor_sync(0xffffffffu, sum, 2);
        const float inv = 1.0f / sum;
#pragma unroll
        for (int jj = 0; jj < 16; jj++) psh[i][lg + 4 * jj] = s[jj] * inv;
        __syncwarp();

        float o[8];
#pragma unroll
        for (int r = 0; r < 8; r++) o[r] = 0.0f;
#pragma unroll
        for (int j = 0; j < 64; j++) {
            const float p = psh[i][j];
            const float4 v0 = *(const float4*)&vsh[j][lg * 8];
            const float4 v1 = *(const float4*)&vsh[j][lg * 8 + 4];
            o[0] += p * v0.x; o[1] += p * v0.y; o[2] += p * v0.z; o[3] += p * v0.w;
            o[4] += p * v1.x; o[5] += p * v1.y; o[6] += p * v1.z; o[7] += p * v1.w;
        }
        __nv_bfloat162* og = (__nv_bfloat162*)(out + tok_i * 512 + h * 32 + lg * 8);
        og[0] = __floats2bfloat162_rn(o[0], o[1]);
        og[1] = __floats2bfloat162_rn(o[2], o[3]);
        og[2] = __floats2bfloat162_rn(o[4], o[5]);
        og[3] = __floats2bfloat162_rn(o[6], o[7]);
    }
}

// ---------------------------------------------------------------------------
// Launch
// ---------------------------------------------------------------------------
#define GEMM_SMEM (3 * 32768)

extern "C" void kernel_launch(void* const* d_in, const int* in_sizes, int n_in,
                              void* d_out, int out_size) {
    const float* x      = (const float*)d_in[0];
    const float* D      = (const float*)d_in[1];
    const float* n1g    = (const float*)d_in[2];
    const float* n1b    = (const float*)d_in[3];
    const float* qkv_w  = (const float*)d_in[4];
    const float* qkv_b  = (const float*)d_in[5];
    const float* proj_w = (const float*)d_in[6];
    const float* proj_b = (const float*)d_in[7];
    const float* a_p    = (const float*)d_in[8];
    const float* b_p    = (const float*)d_in[9];
    const float* a_r    = (const float*)d_in[10];
    const float* b_r    = (const float*)d_in[11];
    const float* n2g    = (const float*)d_in[12];
    const float* n2b    = (const float*)d_in[13];
    const float* fc1_w  = (const float*)d_in[14];
    const float* fc1_b  = (const float*)d_in[15];
    const float* fc2_w  = (const float*)d_in[16];
    const float* fc2_b  = (const float*)d_in[17];
    float* out = (float*)d_out;

    __nv_bfloat16 *p_xnb, *p_attb, *p_hb, *p_wqkv, *p_wproj, *p_wfc1, *p_wfc2;
    float *p_qkv, *p_x2;
    cudaGetSymbolAddress((void**)&p_xnb,   g_xnb);
    cudaGetSymbolAddress((void**)&p_qkv,   g_qkv);
    cudaGetSymbolAddress((void**)&p_attb,  g_attb);
    cudaGetSymbolAddress((void**)&p_x2,    g_x2);
    cudaGetSymbolAddress((void**)&p_hb,    g_hb);
    cudaGetSymbolAddress((void**)&p_wqkv,  g_wqkv);
    cudaGetSymbolAddress((void**)&p_wproj, g_wproj);
    cudaGetSymbolAddress((void**)&p_wfc1,  g_wfc1);
    cudaGetSymbolAddress((void**)&p_wfc2,  g_wfc2);

    cudaFuncSetAttribute(gemm_bf16<0, float>,         cudaFuncAttributeMaxDynamicSharedMemorySize, GEMM_SMEM);
    cudaFuncSetAttribute(gemm_bf16<1, float>,         cudaFuncAttributeMaxDynamicSharedMemorySize, GEMM_SMEM);
    cudaFuncSetAttribute(gemm_bf16<2, __nv_bfloat16>, cudaFuncAttributeMaxDynamicSharedMemorySize, GEMM_SMEM);

    const int M = MTOK;

    // 0. weights -> bf16
    cvt_kernel<<<(1536 * 512 / 4 + 255) / 256, 256>>>(qkv_w,  p_wqkv,  1536 * 512 / 4);
    cvt_kernel<<<(512  * 512 / 4 + 255) / 256, 256>>>(proj_w, p_wproj, 512  * 512 / 4);
    cvt_kernel<<<(2048 * 512 / 4 + 255) / 256, 256>>>(fc1_w,  p_wfc1,  2048 * 512 / 4);
    cvt_kernel<<<(512 * 2048 / 4 + 255) / 256, 256>>>(fc2_w,  p_wfc2,  512 * 2048 / 4);

    // 1. LN1 -> bf16
    ln_kernel<<<M, 128>>>(x, n1g, n1b, p_xnb);
    // 2. QKV  (grid: x = N-tiles, y = M-bands)
    gemm_bf16<0, float><<<dim3(12, M / 128), 256, GEMM_SMEM>>>(p_xnb, p_wqkv, qkv_b, nullptr, p_qkv, M, 1536, 512);
    // 3. attention
    attn_kernel<<<NWIN, 256>>>(p_qkv, D, a_p, b_p, a_r, b_r, p_attb);
    // 4. proj + residual(x)
    gemm_bf16<1, float><<<dim3(4, M / 128), 256, GEMM_SMEM>>>(p_attb, p_wproj, proj_b, x, p_x2, M, 512, 512);
    // 5. LN2 -> bf16
    ln_kernel<<<M, 128>>>(p_x2, n2g, n2b, p_xnb);
    // 6. fc1 + GELU -> bf16
    gemm_bf16<2, __nv_bfloat16><<<dim3(16, M / 128), 256, GEMM_SMEM>>>(p_xnb, p_wfc1, fc1_b, nullptr, p_hb, M, 2048, 512);
    // 7. fc2 + residual(x2) -> out
    gemm_bf16<1, float><<<dim3(4, M / 128), 256, GEMM_SMEM>>>(p_hb, p_wfc2, fc2_b, p_x2, out, M, 512, 2048);
}

// round 15
// speedup vs baseline: 1.1132x; 1.0118x over previous
#include <cuda_runtime.h>
#include <cuda_bf16.h>
#include <cstdint>

// ---------------------------------------------------------------------------
// Problem constants
// ---------------------------------------------------------------------------
#define MTOK 65536          // tokens
#define CDIM 512
#define NHEADS 16
#define NWIN 1024
#define NW 64

// Scratch (device globals — no allocation allowed)
__device__ __nv_bfloat16 g_xnb [MTOK * CDIM];      // LN output (bf16 GEMM A)
__device__ __nv_bfloat16 g_qkvb[MTOK * 3 * CDIM];  // qkv (bf16)
__device__ __nv_bfloat16 g_attb[MTOK * CDIM];      // attention out (bf16)
__device__ float         g_x2  [MTOK * CDIM];      // residual 1 (fp32)
__device__ __nv_bfloat16 g_hb  [MTOK * 4 * CDIM];  // fc1/gelu out (bf16)
__device__ __nv_bfloat16 g_wqkv [1536 * 512];
__device__ __nv_bfloat16 g_wproj[512 * 512];
__device__ __nv_bfloat16 g_wfc1 [2048 * 512];
__device__ __nv_bfloat16 g_wfc2 [512 * 2048];

// ---------------------------------------------------------------------------
// PTX helpers
// ---------------------------------------------------------------------------
__device__ __forceinline__ void cp_async16(uint32_t s, const void* g) {
    asm volatile("cp.async.cg.shared.global [%0], [%1], 16;\n" :: "r"(s), "l"(g));
}
__device__ __forceinline__ void cp_commit() {
    asm volatile("cp.async.commit_group;\n");
}
template<int N> __device__ __forceinline__ void cp_wait() {
    asm volatile("cp.async.wait_group %0;\n" :: "n"(N));
}
__device__ __forceinline__ uint32_t smem_u32(const void* p) {
    uint32_t a;
    asm("{ .reg .u64 t; cvta.to.shared.u64 t, %1; cvt.u32.u64 %0, t; }" : "=r"(a) : "l"(p));
    return a;
}
__device__ __forceinline__ void ldsm_x4(uint32_t& r0, uint32_t& r1, uint32_t& r2, uint32_t& r3,
                                        uint32_t addr) {
    asm volatile("ldmatrix.sync.aligned.m8n8.x4.shared.b16 {%0,%1,%2,%3}, [%4];"
                 : "=r"(r0), "=r"(r1), "=r"(r2), "=r"(r3) : "r"(addr));
}
__device__ __forceinline__ void mma_bf16(float c[4], const uint32_t a[4], const uint32_t b[2]) {
    asm volatile(
        "mma.sync.aligned.m16n8k16.row.col.f32.bf16.bf16.f32 "
        "{%0,%1,%2,%3},{%4,%5,%6,%7},{%8,%9},{%0,%1,%2,%3};\n"
        : "+f"(c[0]), "+f"(c[1]), "+f"(c[2]), "+f"(c[3])
        : "r"(a[0]), "r"(a[1]), "r"(a[2]), "r"(a[3]), "r"(b[0]), "r"(b[1]));
}
__device__ __forceinline__ float gelu_exact(float x) {
    return 0.5f * x * (1.0f + erff(x * 0.7071067811865475f));
}
__device__ __forceinline__ float2 bf2_to_f2(uint32_t u) {
    __nv_bfloat162 h = *reinterpret_cast<__nv_bfloat162*>(&u);
    return __bfloat1622float2(h);
}

// ---------------------------------------------------------------------------
// bf16 GEMM: Y[m][n] = sum_k A[m][k] * W[n][k] + bias[n] (+epi)
// OP: 0 = bias, 1 = bias + res(fp32), 2 = bias + exact GELU
// Grid: (N/128, M/128), x = N-tile fast-varying (A band shared via L2).
// BM=BN=128, BK=64 halves (128B rows, 8x16B segs, XOR swizzle seg^=(row&7)),
// 3-stage cp.async ring in 96KB dynamic smem, one __syncthreads per 64-K slab.
// 8 warps (4 M x 2 N), warp tile 32x64 via m16n8k16.
// ---------------------------------------------------------------------------
template<int OP, typename OutT>
__global__ __launch_bounds__(256, 2)
void gemm_bf16(const __nv_bfloat16* __restrict__ A, const __nv_bfloat16* __restrict__ W,
               const float* __restrict__ bias, const float* __restrict__ res,
               OutT* __restrict__ Y, int M, int N, int K) {
    constexpr int STAGE = 32768;              // A 16KB + B 16KB
    extern __shared__ __align__(1024) char tiles[];   // 3 * STAGE = 96KB

    const int tid = threadIdx.x;
    const int bm = blockIdx.y * 128;          // M-band (slow-varying)
    const int bn = blockIdx.x * 128;          // N-tile (fast-varying)
    const int warp = tid >> 5, lane = tid & 31;
    const int wm = (warp >> 1) * 32;
    const int wn = (warp & 1) * 64;
    const int fr = lane >> 2;
    const int fc2 = (lane & 3) * 2;

    float c[2][8][4];
#pragma unroll
    for (int mt = 0; mt < 2; mt++)
#pragma unroll
        for (int nt = 0; nt < 8; nt++)
#pragma unroll
            for (int r = 0; r < 4; r++) c[mt][nt][r] = 0.0f;

    const int nk = K >> 6;                    // 64-wide K slabs
    const uint32_t sbase = smem_u32(tiles);

    const int ldRow = tid >> 3;               // 0..31
    const int ldC   = tid & 7;                // 16B seg within 128B row
    auto load_tile = [&](int kt, int stage) {
        const int k0 = kt * 64;
        const uint32_t sb = sbase + stage * STAGE;
#pragma unroll
        for (int q = 0; q < 4; q++) {
            const int row = ldRow + q * 32;
            const int seg = ldC ^ (row & 7);
            cp_async16(sb + row * 128 + seg * 16,
                       A + (size_t)(bm + row) * K + k0 + ldC * 8);
            cp_async16(sb + 16384 + row * 128 + seg * 16,
                       W + (size_t)(bn + row) * K + k0 + ldC * 8);
        }
        cp_commit();
    };

    const int lRow = lane & 15;
    const int lSeg = lane >> 4;
    uint32_t offA[2][4], offB[4][4];
#pragma unroll
    for (int mt = 0; mt < 2; mt++) {
        const int row = wm + mt * 16 + lRow;
        const int sw = row & 7;
#pragma unroll
        for (int ks = 0; ks < 4; ks++)
            offA[mt][ks] = row * 128 + (((ks * 2 + lSeg) ^ sw) << 4);
    }
#pragma unroll
    for (int g = 0; g < 4; g++) {
        const int row = wn + g * 16 + lRow;
        const int sw = row & 7;
#pragma unroll
        for (int ks = 0; ks < 4; ks++)
            offB[g][ks] = 16384 + row * 128 + (((ks * 2 + lSeg) ^ sw) << 4);
    }

    load_tile(0, 0);
    if (nk > 1) load_tile(1, 1);

    for (int kt = 0; kt < nk; kt++) {
        if (kt < nk - 1) cp_wait<1>(); else cp_wait<0>();
        __syncthreads();
        if (kt + 2 < nk) load_tile(kt + 2, (kt + 2) % 3);
        const uint32_t sb = sbase + (kt % 3) * STAGE;
#pragma unroll
        for (int ks = 0; ks < 4; ks++) {
            uint32_t af[2][4], bf[8][2];
#pragma unroll
            for (int mt = 0; mt < 2; mt++)
                ldsm_x4(af[mt][0], af[mt][1], af[mt][2], af[mt][3], sb + offA[mt][ks]);
#pragma unroll
            for (int g = 0; g < 4; g++)
                ldsm_x4(bf[2 * g][0], bf[2 * g + 1][0], bf[2 * g][1], bf[2 * g + 1][1],
                        sb + offB[g][ks]);
#pragma unroll
            for (int mt = 0; mt < 2; mt++)
#pragma unroll
                for (int nt = 0; nt < 8; nt++)
                    mma_bf16(c[mt][nt], af[mt], bf[nt]);
        }
    }

    // epilogue (m16n8 accum layout)
#pragma unroll
    for (int mt = 0; mt < 2; mt++) {
#pragma unroll
        for (int nt = 0; nt < 8; nt++) {
            const int n0 = bn + wn + nt * 8 + fc2;
            const float2 b2 = *(const float2*)&bias[n0];
#pragma unroll
            for (int half = 0; half < 2; half++) {
                const int m0 = bm + wm + mt * 16 + fr + half * 8;
                float v0 = c[mt][nt][half * 2 + 0] + b2.x;
                float v1 = c[mt][nt][half * 2 + 1] + b2.y;
                if constexpr (OP == 1) {
                    const float2 r2 = *(const float2*)&res[(size_t)m0 * N + n0];
                    v0 += r2.x; v1 += r2.y;
                }
                if constexpr (OP == 2) {
                    v0 = gelu_exact(v0); v1 = gelu_exact(v1);
                }
                if constexpr (sizeof(OutT) == 4) {
                    *(float2*)&Y[(size_t)m0 * N + n0] = make_float2(v0, v1);
                } else {
                    *(__nv_bfloat162*)&Y[(size_t)m0 * N + n0] = __floats2bfloat162_rn(v0, v1);
                }
            }
        }
    }
}

// ---------------------------------------------------------------------------
// fp32 -> bf16 weight conversion
// ---------------------------------------------------------------------------
__global__ __launch_bounds__(256)
void cvt_kernel(const float* __restrict__ in, __nv_bfloat16* __restrict__ out, int n4) {
    const int i = blockIdx.x * blockDim.x + threadIdx.x;
    if (i < n4) {
        const float4 v = ((const float4*)in)[i];
        ((__nv_bfloat162*)out)[i * 2]     = __floats2bfloat162_rn(v.x, v.y);
        ((__nv_bfloat162*)out)[i * 2 + 1] = __floats2bfloat162_rn(v.z, v.w);
    }
}

// ---------------------------------------------------------------------------
// LayerNorm -> bf16
// ---------------------------------------------------------------------------
__global__ __launch_bounds__(128)
void ln_kernel(const float* __restrict__ x, const float* __restrict__ g,
               const float* __restrict__ b, __nv_bfloat16* __restrict__ y) {
    const int row = blockIdx.x;
    const int t = threadIdx.x;
    const float4 v = ((const float4*)(x + (size_t)row * CDIM))[t];
    float s = v.x + v.y + v.z + v.w;
    float q = v.x * v.x + v.y * v.y + v.z * v.z + v.w * v.w;
#pragma unroll
    for (int o = 16; o; o >>= 1) {
        s += __shfl_xor_sync(0xffffffffu, s, o);
        q += __shfl_xor_sync(0xffffffffu, q, o);
    }
    __shared__ float ss[4], qq[4];
    if ((t & 31) == 0) { ss[t >> 5] = s; qq[t >> 5] = q; }
    __syncthreads();
    s = ss[0] + ss[1] + ss[2] + ss[3];
    q = qq[0] + qq[1] + qq[2] + qq[3];
    const float mean = s * (1.0f / CDIM);
    const float var = q * (1.0f / CDIM) - mean * mean;
    const float rstd = rsqrtf(var + 1e-5f);
    const float4 gg = ((const float4*)g)[t];
    const float4 bb = ((const float4*)b)[t];
    const float o0 = (v.x - mean) * rstd * gg.x + bb.x;
    const float o1 = (v.y - mean) * rstd * gg.y + bb.y;
    const float o2 = (v.z - mean) * rstd * gg.z + bb.z;
    const float o3 = (v.w - mean) * rstd * gg.w + bb.w;
    __nv_bfloat162* yp = (__nv_bfloat162*)(y + (size_t)row * CDIM);
    yp[t * 2]     = __floats2bfloat162_rn(o0, o1);
    yp[t * 2 + 1] = __floats2bfloat162_rn(o2, o3);
}

// ---------------------------------------------------------------------------
// Windowed attention (bf16 qkv in, fp32 math, bf16 out)
// ---------------------------------------------------------------------------
__global__ __launch_bounds__(256)
void attn_kernel(const __nv_bfloat16* __restrict__ qkv, const float* __restrict__ D,
                 const float* __restrict__ a_p, const float* __restrict__ b_p,
                 const float* __restrict__ a_r, const float* __restrict__ b_r,
                 __nv_bfloat16* __restrict__ out) {
    __shared__ float  Dsh[64];
    __shared__ float2 csT[15][64];
    __shared__ float  ksh[64][36];
    __shared__ float  vsh[64][36];
    __shared__ float  psh[64][65];
    __shared__ float  phiT[15], arT[15], brT[15];

    const int t = threadIdx.x;
    const int w = blockIdx.x;
    const int bb = w >> 6;
    const int ww = w & 63;
    const int wy = ww >> 3, wx = ww & 7;

    if (t < 64) {
        const int y = wy * 8 + (t >> 3), xc = wx * 8 + (t & 7);
        Dsh[t] = D[bb * 4096 + y * 64 + xc];
    }
    __syncthreads();
    for (int e = t; e < 15 * 64; e += 256) {
        const int r7 = e >> 6, j = e & 63;
        const float ang = (float)(r7 - 7) * Dsh[j] * (6.283185307179586f / 256.0f);
        float sn, cs;
        sincosf(ang, &sn, &cs);
        csT[r7][j] = make_float2(cs, sn);
    }

    const int i  = t >> 2;
    const int lg = t & 3;
    const int y_i = wy * 8 + (i >> 3), x_i = wx * 8 + (i & 7);
    const long tok_i = (long)bb * 4096 + y_i * 64 + x_i;
    const int ri = i >> 3, ci = i & 7;

    for (int h = 0; h < NHEADS; h++) {
        __syncthreads();
        {
            // 8 bf16 halves = 16B per thread for k and v
            const __nv_bfloat16* kg = qkv + tok_i * 1536 + 512 + h * 32 + lg * 8;
            const uint4 kr = *(const uint4*)kg;
            const uint4 vr = *(const uint4*)(kg + 512);
            const float2 k0 = bf2_to_f2(kr.x), k1 = bf2_to_f2(kr.y);
            const float2 k2 = bf2_to_f2(kr.z), k3 = bf2_to_f2(kr.w);
            const float2 v0 = bf2_to_f2(vr.x), v1 = bf2_to_f2(vr.y);
            const float2 v2 = bf2_to_f2(vr.z), v3 = bf2_to_f2(vr.w);
            *(float4*)&ksh[i][lg * 8]     = make_float4(k0.x, k0.y, k1.x, k1.y);
            *(float4*)&ksh[i][lg * 8 + 4] = make_float4(k2.x, k2.y, k3.x, k3.y);
            *(float4*)&vsh[i][lg * 8]     = make_float4(v0.x, v0.y, v1.x, v1.y);
            *(float4*)&vsh[i][lg * 8 + 4] = make_float4(v2.x, v2.y, v3.x, v3.y);
        }
        if (t < 15) {
            const int idx = (t + 8) % 15;
            const float azf = (float)(t - 7) * (6.283185307179586f / 64.0f);
            float sa, ca;
            sincosf(azf, &sa, &ca);
            phiT[t] = a_p[idx * NHEADS + h] * ca + b_p[idx * NHEADS + h] * sa;
            arT[t]  = a_r[idx * NHEADS + h];
            brT[t]  = b_r[idx * NHEADS + h];
        }
        float qv[32];
        {
            // full head: 32 bf16 = 64 bytes = 4 x uint4
            const __nv_bfloat16* qg = qkv + tok_i * 1536 + h * 32;
            const uint4 q0 = ((const uint4*)qg)[0];
            const uint4 q1 = ((const uint4*)qg)[1];
            const uint4 q2 = ((const uint4*)qg)[2];
            const uint4 q3 = ((const uint4*)qg)[3];
            const uint32_t qw[16] = {q0.x, q0.y, q0.z, q0.w, q1.x, q1.y, q1.z, q1.w,
                                     q2.x, q2.y, q2.z, q2.w, q3.x, q3.y, q3.z, q3.w};
#pragma unroll
            for (int p = 0; p < 16; p++) {
                const float2 f = bf2_to_f2(qw[p]);
                qv[p * 2 + 0] = f.x * 0.17677669529663687f;
                qv[p * 2 + 1] = f.y * 0.17677669529663687f;
            }
        }
        __syncthreads();

        float s[16];
#pragma unroll
        for (int jj = 0; jj < 16; jj++) {
            const int j = lg + 4 * jj;
            float acc = 0.0f;
#pragma unroll
            for (int d4 = 0; d4 < 8; d4++) {
                const float4 kk = *(const float4*)&ksh[j][d4 * 4];
                acc += qv[d4 * 4 + 0] * kk.x + qv[d4 * 4 + 1] * kk.y
                     + qv[d4 * 4 + 2] * kk.z + qv[d4 * 4 + 3] * kk.w;
            }
            const int r7 = ri - (j >> 3) + 7;
            const int a7 = ci - (j & 7) + 7;
            const float2 cp = csT[r7][j];
            acc += phiT[a7] + arT[r7] * cp.x + brT[r7] * cp.y;
            s[jj] = acc;
        }
        float mx = s[0];
#pragma unroll
        for (int jj = 1; jj < 16; jj++) mx = fmaxf(mx, s[jj]);
        mx = fmaxf(mx, __shfl_xor_sync(0xffffffffu, mx, 1));
        mx = fmaxf(mx, __shfl_xor_sync(0xffffffffu, mx, 2));
        float sum = 0.0f;
#pragma unroll
        for (int jj = 0; jj < 16; jj++) { s[jj] = __expf(s[jj] - mx); sum += s[jj]; }
        sum += __shfl_xor_sync(0xffffffffu, sum, 1);
        sum += __shfl_xor_sync(0xffffffffu, sum, 2);
        const float inv = 1.0f / sum;
#pragma unroll
        for (int jj = 0; jj < 16; jj++) psh[i][lg + 4 * jj] = s[jj] * inv;
        __syncwarp();

        float o[8];
#pragma unroll
        for (int r = 0; r < 8; r++) o[r] = 0.0f;
#pragma unroll
        for (int j = 0; j < 64; j++) {
            const float p = psh[i][j];
            const float4 v0 = *(const float4*)&vsh[j][lg * 8];
            const float4 v1 = *(const float4*)&vsh[j][lg * 8 + 4];
            o[0] += p * v0.x; o[1] += p * v0.y; o[2] += p * v0.z; o[3] += p * v0.w;
            o[4] += p * v1.x; o[5] += p * v1.y; o[6] += p * v1.z; o[7] += p * v1.w;
        }
        __nv_bfloat162* og = (__nv_bfloat162*)(out + tok_i * 512 + h * 32 + lg * 8);
        og[0] = __floats2bfloat162_rn(o[0], o[1]);
        og[1] = __floats2bfloat162_rn(o[2], o[3]);
        og[2] = __floats2bfloat162_rn(o[4], o[5]);
        og[3] = __floats2bfloat162_rn(o[6], o[7]);
    }
}

// ---------------------------------------------------------------------------
// Launch
// ---------------------------------------------------------------------------
#define GEMM_SMEM (3 * 32768)

extern "C" void kernel_launch(void* const* d_in, const int* in_sizes, int n_in,
                              void* d_out, int out_size) {
    const float* x      = (const float*)d_in[0];
    const float* D      = (const float*)d_in[1];
    const float* n1g    = (const float*)d_in[2];
    const float* n1b    = (const float*)d_in[3];
    const float* qkv_w  = (const float*)d_in[4];
    const float* qkv_b  = (const float*)d_in[5];
    const float* proj_w = (const float*)d_in[6];
    const float* proj_b = (const float*)d_in[7];
    const float* a_p    = (const float*)d_in[8];
    const float* b_p    = (const float*)d_in[9];
    const float* a_r    = (const float*)d_in[10];
    const float* b_r    = (const float*)d_in[11];
    const float* n2g    = (const float*)d_in[12];
    const float* n2b    = (const float*)d_in[13];
    const float* fc1_w  = (const float*)d_in[14];
    const float* fc1_b  = (const float*)d_in[15];
    const float* fc2_w  = (const float*)d_in[16];
    const float* fc2_b  = (const float*)d_in[17];
    float* out = (float*)d_out;

    __nv_bfloat16 *p_xnb, *p_qkvb, *p_attb, *p_hb, *p_wqkv, *p_wproj, *p_wfc1, *p_wfc2;
    float *p_x2;
    cudaGetSymbolAddress((void**)&p_xnb,   g_xnb);
    cudaGetSymbolAddress((void**)&p_qkvb,  g_qkvb);
    cudaGetSymbolAddress((void**)&p_attb,  g_attb);
    cudaGetSymbolAddress((void**)&p_x2,    g_x2);
    cudaGetSymbolAddress((void**)&p_hb,    g_hb);
    cudaGetSymbolAddress((void**)&p_wqkv,  g_wqkv);
    cudaGetSymbolAddress((void**)&p_wproj, g_wproj);
    cudaGetSymbolAddress((void**)&p_wfc1,  g_wfc1);
    cudaGetSymbolAddress((void**)&p_wfc2,  g_wfc2);

    cudaFuncSetAttribute(gemm_bf16<0, __nv_bfloat16>, cudaFuncAttributeMaxDynamicSharedMemorySize, GEMM_SMEM);
    cudaFuncSetAttribute(gemm_bf16<1, float>,         cudaFuncAttributeMaxDynamicSharedMemorySize, GEMM_SMEM);
    cudaFuncSetAttribute(gemm_bf16<2, __nv_bfloat16>, cudaFuncAttributeMaxDynamicSharedMemorySize, GEMM_SMEM);

    const int M = MTOK;

    // 0. weights -> bf16
    cvt_kernel<<<(1536 * 512 / 4 + 255) / 256, 256>>>(qkv_w,  p_wqkv,  1536 * 512 / 4);
    cvt_kernel<<<(512  * 512 / 4 + 255) / 256, 256>>>(proj_w, p_wproj, 512  * 512 / 4);
    cvt_kernel<<<(2048 * 512 / 4 + 255) / 256, 256>>>(fc1_w,  p_wfc1,  2048 * 512 / 4);
    cvt_kernel<<<(512 * 2048 / 4 + 255) / 256, 256>>>(fc2_w,  p_wfc2,  512 * 2048 / 4);

    // 1. LN1 -> bf16
    ln_kernel<<<M, 128>>>(x, n1g, n1b, p_xnb);
    // 2. QKV -> bf16
    gemm_bf16<0, __nv_bfloat16><<<dim3(12, M / 128), 256, GEMM_SMEM>>>(p_xnb, p_wqkv, qkv_b, nullptr, p_qkvb, M, 1536, 512);
    // 3. attention (bf16 in/out, fp32 math)
    attn_kernel<<<NWIN, 256>>>(p_qkvb, D, a_p, b_p, a_r, b_r, p_attb);
    // 4. proj + residual(x)
    gemm_bf16<1, float><<<dim3(4, M / 128), 256, GEMM_SMEM>>>(p_attb, p_wproj, proj_b, x, p_x2, M, 512, 512);
    // 5. LN2 -> bf16
    ln_kernel<<<M, 128>>>(p_x2, n2g, n2b, p_xnb);
    // 6. fc1 + GELU -> bf16
    gemm_bf16<2, __nv_bfloat16><<<dim3(16, M / 128), 256, GEMM_SMEM>>>(p_xnb, p_wfc1, fc1_b, nullptr, p_hb, M, 2048, 512);
    // 7. fc2 + residual(x2) -> out
    gemm_bf16<1, float><<<dim3(4, M / 128), 256, GEMM_SMEM>>>(p_hb, p_wfc2, fc2_b, p_x2, out, M, 512, 2048);
}